// round 15
// baseline (speedup 1.0000x reference)
#include <cuda_runtime.h>
#include <math.h>

typedef unsigned long long u64;
#define DI __device__ __forceinline__

// ---------------- f32x2 helpers ----------------
DI u64 pack2(float lo, float hi) {
    u64 r; asm("mov.b64 %0, {%1, %2};" : "=l"(r) : "f"(lo), "f"(hi)); return r;
}
DI void unpack2(u64 v, float& lo, float& hi) {
    asm("mov.b64 {%0, %1}, %2;" : "=f"(lo), "=f"(hi) : "l"(v));
}
DI u64 fma2(u64 a, u64 b, u64 c) {
    u64 d; asm("fma.rn.f32x2 %0, %1, %2, %3;" : "=l"(d) : "l"(a), "l"(b), "l"(c));
    return d;
}

// ---------------- scratch ----------------
__device__ float g_bufA[13778944];
__device__ float g_bufB[13778944];
__device__ float g_off [18113536];
__device__ u64   g_wpk [70464];     // off-conv weight pairs, [(c*KK+kk)*OCP+p]
__device__ u64   g_wdef[16800];     // deform weight pairs (transposed)

// off-conv segment bases (u64)
#define O1 0
#define O2 81
#define O3 1377
#define O4 21377
#define O5 59793
#define O6 69793
#define OTOT 70441
// deform segment bases (u64)
#define E1 0
#define E2 72
#define E3 2376
#define E4 8776
#define E5 15048
#define E6 16648
#define ETOT 16792
#define PACK_TOTAL (OTOT + ETOT)

struct PackArgs {
    const float *ow1, *ow2, *ow3, *ow4, *ow5, *ow6;
    const float *ww1, *ww2, *ww3, *ww4, *ww5, *ww6;
};

__global__ void __launch_bounds__(256) pack_all_k(
    PackArgs a, u64* __restrict__ wpk, u64* __restrict__ wdef)
{
    int i = blockIdx.x * 256 + threadIdx.x;
    if (i >= PACK_TOTAL) return;

    if (i < OTOT) {
        auto pw = [&](const float* ow, int base, int OCP, int KK, int CI) {
            int j = i - base;
            int p = j % OCP;
            int t = j / OCP;
            int kk = t % KK, c = t / KK;
            int CIKK = CI * KK;
            wpk[i] = pack2(ow[(2 * p) * CIKK + c * KK + kk],
                           ow[(2 * p + 1) * CIKK + c * KK + kk]);
        };
        if      (i < O2) pw(a.ow1, O1,  9,  9,  1);
        else if (i < O3) pw(a.ow2, O2,  9,  9, 16);
        else if (i < O4) pw(a.ow3, O3, 25, 25, 32);
        else if (i < O5) pw(a.ow4, O4, 49, 49, 16);
        else if (i < O6) pw(a.ow5, O5, 25, 25, 16);
        else             pw(a.ow6, O6,  9,  9,  8);
    } else {
        int e = i - OTOT;
        auto pt = [&](const float* w, int base, int COH, int CI, int KK) {
            int j = e - base; int q = j / COH, ocp = j - q * COH;
            int k = q / CI, c = q - k * CI;
            wdef[e] = pack2(w[((2 * ocp) * CI + c) * KK + k],
                            w[((2 * ocp + 1) * CI + c) * KK + k]);
        };
        if      (e < E2) pt(a.ww1, E1,  8,  1,  9);
        else if (e < E3) pt(a.ww2, E2, 16, 16,  9);
        else if (e < E4) pt(a.ww3, E3,  8, 32, 25);
        else if (e < E5) pt(a.ww4, E4,  8, 16, 49);
        else if (e < E6) pt(a.ww5, E5,  4, 16, 25);
        else             pt(a.ww6, E6,  2,  8,  9);
    }
}

// ---------------- offset conv: PT oc-pairs x 8 px, pipelined weights --------
// NTH = threads per block (128 -> 4 CTAs/SM, 256 -> 2 CTAs/SM).
template<int CI, int K, int H, int SLICES, int PT, int NTH>
__global__ void __launch_bounds__(NTH, 512 / NTH) off_conv_k(
    const float* __restrict__ in, const u64* __restrict__ wpk,
    const float* __restrict__ ob, float* __restrict__ off)
{
    constexpr int W = H, Ho = H - K + 1, Wo = Ho, P = Ho * Wo, HW = H * W;
    constexpr int KK = K * K, OCP = KK;
    constexpr int NT   = (OCP + PT - 1) / PT;
    constexpr int ROWS = (Ho + SLICES - 1) / SLICES;
    constexpr int RIN  = ROWS + K - 1;
    constexpr int QW   = (Wo + 7) / 8;
    constexpr int WP   = (W + 10) & ~3;
    constexpr int NQ   = (K + 10) / 4;

    extern __shared__ float img[];   // CI * WP * RIN
    int b = blockIdx.x;
    int y0 = blockIdx.y * ROWS;
    int rows = min(ROWS, Ho - y0);

    {
        int rin = rows + K - 1;
        const float* inb = in + (long)b * CI * HW + y0 * W;
        int tot = CI * rin * W;
        for (int i = threadIdx.x; i < tot; i += NTH) {
            int c  = i / (rin * W);
            int r2 = i - c * rin * W;
            int r  = r2 / W;
            int col = r2 - r * W;
            img[(c * RIN + r) * WP + col] = inb[c * HW + r * W + col];
        }
    }
    __syncthreads();

    float* offb = off + (long)b * (2 * KK) * P;
    int items = NT * rows * QW;

    for (int item = threadIdx.x; item < items; item += NTH) {
        int qx = item % QW;
        int t  = item / QW;
        int ly = t % rows;
        int pt = t / rows;
        int x0 = qx * 8;

        int p[PT];
        #pragma unroll
        for (int i = 0; i < PT; i++) p[i] = min(pt * PT + i, OCP - 1);

        u64 acc[PT][8];
        #pragma unroll
        for (int i = 0; i < PT; i++) {
            u64 bini = pack2(__ldg(ob + 2 * p[i]), __ldg(ob + 2 * p[i] + 1));
            #pragma unroll
            for (int j = 0; j < 8; j++) acc[i][j] = bini;
        }

        // pipelined weight stream over flattened (c*KK + kk)
        u64 wv[PT];
        #pragma unroll
        for (int i = 0; i < PT; i++) wv[i] = __ldg(wpk + p[i]);

        #pragma unroll 1
        for (int c = 0; c < CI; c++) {
            const float* s0 = img + (c * RIN + ly) * WP + x0;
            const u64* wc = wpk + (long)c * KK * OCP;
            #pragma unroll
            for (int ky = 0; ky < K; ky++) {
                const float* sr = s0 + ky * WP;
                u64 pv[K + 7];
                #pragma unroll
                for (int q = 0; q < NQ; q++) {
                    float4 f = *reinterpret_cast<const float4*>(sr + 4 * q);
                    if (4 * q     < K + 7) pv[4 * q]     = pack2(f.x, f.x);
                    if (4 * q + 1 < K + 7) pv[4 * q + 1] = pack2(f.y, f.y);
                    if (4 * q + 2 < K + 7) pv[4 * q + 2] = pack2(f.z, f.z);
                    if (4 * q + 3 < K + 7) pv[4 * q + 3] = pack2(f.w, f.w);
                }
                #pragma unroll
                for (int kx = 0; kx < K; kx++) {
                    // prefetch next flat step's weights (valid across c bound;
                    // final over-read stays inside g_wpk)
                    const u64* wn = wc + (ky * K + kx + 1) * OCP;
                    u64 wnx[PT];
                    #pragma unroll
                    for (int i = 0; i < PT; i++) wnx[i] = __ldg(wn + p[i]);
                    #pragma unroll
                    for (int i = 0; i < PT; i++) {
                        #pragma unroll
                        for (int j = 0; j < 8; j++)
                            acc[i][j] = fma2(pv[kx + j], wv[i], acc[i][j]);
                    }
                    #pragma unroll
                    for (int i = 0; i < PT; i++) wv[i] = wnx[i];
                }
            }
        }
        int y = y0 + ly;
        #pragma unroll
        for (int j = 0; j < 8; j++) {
            if (x0 + j < Wo) {
                int po = y * Wo + x0 + j;
                #pragma unroll
                for (int i = 0; i < PT; i++) {
                    float a0, a1; unpack2(acc[i][j], a0, a1);
                    offb[(2 * p[i])     * P + po] = a0;
                    offb[(2 * p[i] + 1) * P + po] = a1;
                }
            }
        }
    }
}

// ---------------- deformable conv, CG channel groups (R8/R13 config) --------
template<int CI, int CO, int K, int H, int PIX, bool RELU, int CG>
__global__ void __launch_bounds__(256) deform_k(
    const float* __restrict__ in, const float* __restrict__ off,
    const u64* __restrict__ wt, const float* __restrict__ bias,
    float* __restrict__ out)
{
    constexpr int W = H, Ho = H - K + 1, Wo = Ho, P = Ho * Wo, HW = H * W;
    constexpr int KK = K * K, COH = CO / 2;
    constexpr int NS = KK * CI;
    constexpr int CIG = CI / CG;
    constexpr int WOFF = (CIG * HW + 1) & ~1;

    extern __shared__ float smf[];
    float* img = smf;
    u64* wts = reinterpret_cast<u64*>(smf + WOFF);

    int b = blockIdx.x, tid = threadIdx.x;
    const float* inb = in + (long)b * CI * HW;
    for (int i = tid; i < NS * COH; i += 256) wts[i] = wt[i];

    const float* offb = off + (long)b * (2 * KK) * P;
    float* outb = out + (long)b * CO * P;

    if (CG == 1) {
        for (int i = tid; i < CI * HW; i += 256) img[i] = inb[i];
        __syncthreads();

        for (int p0 = tid; p0 < P; p0 += 256 * PIX) {
            int pp[PIX]; bool pval[PIX]; int yo[PIX], xo[PIX];
            #pragma unroll
            for (int i = 0; i < PIX; i++) {
                int p = p0 + i * 256;
                pval[i] = (p < P);
                p = pval[i] ? p : P - 1;
                pp[i] = p;
                yo[i] = p / Wo;
                xo[i] = p - yo[i] * Wo;
            }

            u64 acc[PIX][COH];
            #pragma unroll
            for (int o = 0; o < COH; o++) {
                u64 bini = pack2(__ldg(bias + 2 * o), __ldg(bias + 2 * o + 1));
                #pragma unroll
                for (int i = 0; i < PIX; i++) acc[i][o] = bini;
            }

            #pragma unroll 1
            for (int ky = 0; ky < K; ky++) {
            #pragma unroll 1
            for (int kx = 0; kx < K; kx++) {
                int k = ky * K + kx;
                int a00[PIX], a01[PIX], a10[PIX], a11[PIX];
                float fya[PIX], fyb[PIX], fxa[PIX], fxb[PIX];
                #pragma unroll
                for (int i = 0; i < PIX; i++) {
                    float oy = __ldg(offb + (2 * k) * P + pp[i]);
                    float ox = __ldg(offb + (2 * k + 1) * P + pp[i]);
                    float py = (float)(ky + yo[i]) + oy;
                    float px = (float)(kx + xo[i]) + ox;
                    float y0f = floorf(py), x0f = floorf(px);
                    float wy = py - y0f, wx = px - x0f;
                    int y0 = (int)y0f, x0 = (int)x0f;
                    fya[i] = (y0 >= 0 && y0 < H)      ? (1.f - wy) : 0.f;
                    fyb[i] = (y0 >= -1 && y0 < H - 1) ? wy : 0.f;
                    fxa[i] = (x0 >= 0 && x0 < W)      ? (1.f - wx) : 0.f;
                    fxb[i] = (x0 >= -1 && x0 < W - 1) ? wx : 0.f;
                    int y0c = min(max(y0, 0), H - 1);
                    int y1c = min(max(y0 + 1, 0), H - 1);
                    int x0c = min(max(x0, 0), W - 1);
                    int x1c = min(max(x0 + 1, 0), W - 1);
                    a00[i] = y0c * W + x0c; a01[i] = y0c * W + x1c;
                    a10[i] = y1c * W + x0c; a11[i] = y1c * W + x1c;
                }
                const u64* wrow = wts + k * CI * COH;
                #pragma unroll 2
                for (int c = 0; c < CI; c++) {
                    const float* ic = img + c * HW;
                    u64 ss[PIX];
                    #pragma unroll
                    for (int i = 0; i < PIX; i++) {
                        float t0 = ic[a00[i]] * fxa[i] + ic[a01[i]] * fxb[i];
                        float t1 = ic[a10[i]] * fxa[i] + ic[a11[i]] * fxb[i];
                        float s  = t0 * fya[i] + t1 * fyb[i];
                        ss[i] = pack2(s, s);
                    }
                    const u64* wc = wrow + c * COH;
                    #pragma unroll
                    for (int o = 0; o < COH; o++) {
                        u64 wv = wc[o];
                        #pragma unroll
                        for (int i = 0; i < PIX; i++)
                            acc[i][o] = fma2(ss[i], wv, acc[i][o]);
                    }
                }
            }}

            #pragma unroll
            for (int i = 0; i < PIX; i++) if (pval[i]) {
                #pragma unroll
                for (int o = 0; o < COH; o++) {
                    float a0, a1; unpack2(acc[i][o], a0, a1);
                    if (RELU) { a0 = fmaxf(a0, 0.f); a1 = fmaxf(a1, 0.f); }
                    outb[(2 * o) * P + pp[i]]     = a0;
                    outb[(2 * o + 1) * P + pp[i]] = a1;
                }
            }
        }
    } else {
        static_assert(CG == 1 || 256 * PIX >= P, "PIX must cover P");
        int pp[PIX]; bool pval[PIX]; int yo[PIX], xo[PIX];
        #pragma unroll
        for (int i = 0; i < PIX; i++) {
            int p = tid + i * 256;
            pval[i] = (p < P);
            p = pval[i] ? p : P - 1;
            pp[i] = p;
            yo[i] = p / Wo;
            xo[i] = p - yo[i] * Wo;
        }

        u64 acc[PIX][COH];
        #pragma unroll
        for (int o = 0; o < COH; o++) {
            u64 bini = pack2(__ldg(bias + 2 * o), __ldg(bias + 2 * o + 1));
            #pragma unroll
            for (int i = 0; i < PIX; i++) acc[i][o] = bini;
        }

        #pragma unroll 1
        for (int g = 0; g < CG; g++) {
            if (g > 0) __syncthreads();
            const float* src = inb + g * CIG * HW;
            for (int i = tid; i < CIG * HW; i += 256) img[i] = src[i];
            __syncthreads();

            #pragma unroll 1
            for (int ky = 0; ky < K; ky++) {
            #pragma unroll 1
            for (int kx = 0; kx < K; kx++) {
                int k = ky * K + kx;
                int a00[PIX], a01[PIX], a10[PIX], a11[PIX];
                float fya[PIX], fyb[PIX], fxa[PIX], fxb[PIX];
                #pragma unroll
                for (int i = 0; i < PIX; i++) {
                    float oy = __ldg(offb + (2 * k) * P + pp[i]);
                    float ox = __ldg(offb + (2 * k + 1) * P + pp[i]);
                    float py = (float)(ky + yo[i]) + oy;
                    float px = (float)(kx + xo[i]) + ox;
                    float y0f = floorf(py), x0f = floorf(px);
                    float wy = py - y0f, wx = px - x0f;
                    int y0 = (int)y0f, x0 = (int)x0f;
                    fya[i] = (y0 >= 0 && y0 < H)      ? (1.f - wy) : 0.f;
                    fyb[i] = (y0 >= -1 && y0 < H - 1) ? wy : 0.f;
                    fxa[i] = (x0 >= 0 && x0 < W)      ? (1.f - wx) : 0.f;
                    fxb[i] = (x0 >= -1 && x0 < W - 1) ? wx : 0.f;
                    int y0c = min(max(y0, 0), H - 1);
                    int y1c = min(max(y0 + 1, 0), H - 1);
                    int x0c = min(max(x0, 0), W - 1);
                    int x1c = min(max(x0 + 1, 0), W - 1);
                    a00[i] = y0c * W + x0c; a01[i] = y0c * W + x1c;
                    a10[i] = y1c * W + x0c; a11[i] = y1c * W + x1c;
                }
                #pragma unroll 2
                for (int cl = 0; cl < CIG; cl++) {
                    const float* ic = img + cl * HW;
                    u64 ss[PIX];
                    #pragma unroll
                    for (int i = 0; i < PIX; i++) {
                        float t0 = ic[a00[i]] * fxa[i] + ic[a01[i]] * fxb[i];
                        float t1 = ic[a10[i]] * fxa[i] + ic[a11[i]] * fxb[i];
                        float s  = t0 * fya[i] + t1 * fyb[i];
                        ss[i] = pack2(s, s);
                    }
                    const u64* wc = wts + (k * CI + g * CIG + cl) * COH;
                    #pragma unroll
                    for (int o = 0; o < COH; o++) {
                        u64 wv = wc[o];
                        #pragma unroll
                        for (int i = 0; i < PIX; i++)
                            acc[i][o] = fma2(ss[i], wv, acc[i][o]);
                    }
                }
            }}
        }

        #pragma unroll
        for (int i = 0; i < PIX; i++) if (pval[i]) {
            #pragma unroll
            for (int o = 0; o < COH; o++) {
                float a0, a1; unpack2(acc[i][o], a0, a1);
                if (RELU) { a0 = fmaxf(a0, 0.f); a1 = fmaxf(a1, 0.f); }
                outb[(2 * o) * P + pp[i]]     = a0;
                outb[(2 * o + 1) * P + pp[i]] = a1;
            }
        }
    }
}

// ---------------- batched FC: 8 batch rows per block ----------------
__global__ void __launch_bounds__(256) fc8_k(
    const float* __restrict__ h, const float* __restrict__ w1,
    const float* __restrict__ b1, const float* __restrict__ w2,
    const float* __restrict__ b2, float* __restrict__ out)
{
    __shared__ float flat[8][676];
    __shared__ float z[8][256];
    int b0 = blockIdx.x * 8, tid = threadIdx.x;
    int lane = tid & 31, wid = tid >> 5;

    for (int i = tid; i < 8 * 676; i += 256) {
        int r = i / 676, c = i - r * 676;
        flat[r][c] = h[(long)(b0 + r) * 676 + c];
    }
    __syncthreads();

    for (int oc = wid; oc < 256; oc += 8) {
        float acc[8];
        #pragma unroll
        for (int r = 0; r < 8; r++) acc[r] = 0.f;
        const float* wr = w1 + (long)oc * 676;
        for (int i = lane; i < 676; i += 32) {
            float w = wr[i];
            #pragma unroll
            for (int r = 0; r < 8; r++) acc[r] += flat[r][i] * w;
        }
        #pragma unroll
        for (int r = 0; r < 8; r++) {
            #pragma unroll
            for (int s = 16; s; s >>= 1)
                acc[r] += __shfl_down_sync(0xffffffffu, acc[r], s);
        }
        if (lane == 0) {
            float bb = b1[oc];
            #pragma unroll
            for (int r = 0; r < 8; r++) z[r][oc] = fmaxf(acc[r] + bb, 0.f);
        }
    }
    __syncthreads();

    for (int oc = wid; oc < 10; oc += 8) {
        float acc[8];
        #pragma unroll
        for (int r = 0; r < 8; r++) acc[r] = 0.f;
        const float* wr = w2 + (long)oc * 256;
        for (int i = lane; i < 256; i += 32) {
            float w = wr[i];
            #pragma unroll
            for (int r = 0; r < 8; r++) acc[r] += z[r][i] * w;
        }
        #pragma unroll
        for (int r = 0; r < 8; r++) {
            #pragma unroll
            for (int s = 16; s; s >>= 1)
                acc[r] += __shfl_down_sync(0xffffffffu, acc[r], s);
        }
        if (lane == 0) {
            float bb = b2[oc];
            #pragma unroll
            for (int r = 0; r < 8; r++)
                out[(long)(b0 + r) * 10 + oc] = acc[r] + bb;
        }
    }
}

// ---------------- host ----------------
template<int CI, int K, int H, int SLICES, int PT, int NTH>
static void launch_off(const float* in, const u64* wpk, const float* ob, float* off)
{
    constexpr int Ho = H - K + 1;
    constexpr int ROWS = (Ho + SLICES - 1) / SLICES;
    constexpr int RIN = ROWS + K - 1;
    constexpr int WP = (H + 10) & ~3;
    constexpr int SM = CI * WP * RIN * 4;
    cudaFuncSetAttribute(off_conv_k<CI, K, H, SLICES, PT, NTH>,
                         cudaFuncAttributeMaxDynamicSharedMemorySize, SM);
    off_conv_k<CI, K, H, SLICES, PT, NTH><<<dim3(512, SLICES), NTH, SM>>>(
        in, wpk, ob, off);
}

template<int CI, int CO, int K, int H, int PIX, bool RELU, int CG>
static void launch_def(const float* in, const float* off, const u64* wt,
                       const float* bias, float* out)
{
    constexpr int CIG = CI / CG;
    constexpr int WOFF = (CIG * H * H + 1) & ~1;
    constexpr int SM = WOFF * 4 + K * K * CI * (CO / 2) * 8;
    cudaFuncSetAttribute(deform_k<CI, CO, K, H, PIX, RELU, CG>,
                         cudaFuncAttributeMaxDynamicSharedMemorySize, SM);
    deform_k<CI, CO, K, H, PIX, RELU, CG><<<512, 256, SM>>>(in, off, wt, bias, out);
}

extern "C" void kernel_launch(void* const* d_in, const int* in_sizes, int n_in,
                              void* d_out, int out_size)
{
    (void)in_sizes; (void)n_in; (void)out_size;
    const float* x = (const float*)d_in[0];
    auto OW = [&](int i) { return (const float*)d_in[4 * i - 3]; };
    auto OB = [&](int i) { return (const float*)d_in[4 * i - 2]; };
    auto WW = [&](int i) { return (const float*)d_in[4 * i - 1]; };
    auto BB = [&](int i) { return (const float*)d_in[4 * i]; };
    const float* fc1w = (const float*)d_in[25];
    const float* fc1b = (const float*)d_in[26];
    const float* fc2w = (const float*)d_in[27];
    const float* fc2b = (const float*)d_in[28];

    float *bufA, *bufB, *off;
    u64 *wpk, *wdef;
    cudaGetSymbolAddress((void**)&bufA, g_bufA);
    cudaGetSymbolAddress((void**)&bufB, g_bufB);
    cudaGetSymbolAddress((void**)&off,  g_off);
    cudaGetSymbolAddress((void**)&wpk,  g_wpk);
    cudaGetSymbolAddress((void**)&wdef, g_wdef);

    PackArgs pa = { OW(1), OW(2), OW(3), OW(4), OW(5), OW(6),
                    WW(1), WW(2), WW(3), WW(4), WW(5), WW(6) };
    pack_all_k<<<(PACK_TOTAL + 255) / 256, 256>>>(pa, wpk, wdef);

    // stage 1: (1 -> 16), K=3, 33 -> 31, relu
    launch_off<1, 3, 33, 1, 3, 256>(x, wpk + O1, OB(1), off);
    launch_def<1, 16, 3, 33, 4, true, 1>(x, off, wdef + E1, BB(1), bufA);
    // stage 2: (16 -> 32), K=3, 31 -> 29, relu  (128-thr, SLICES=2 — R9 win)
    launch_off<16, 3, 31, 2, 3, 128>(bufA, wpk + O2, OB(2), off);
    launch_def<16, 32, 3, 31, 2, true, 1>(bufA, off, wdef + E2, BB(2), bufB);
    // stage 3: (32 -> 16), K=5, 29 -> 25, no relu  (image in 2 channel halves)
    launch_off<32, 5, 29, 2, 3, 256>(bufB, wpk + O3, OB(3), off);
    launch_def<32, 16, 5, 29, 3, false, 2>(bufB, off, wdef + E3, BB(3), bufA);
    // stage 4: (16 -> 16), K=7, 25 -> 19, relu
    launch_off<16, 7, 25, 2, 3, 256>(bufA, wpk + O4, OB(4), off);
    launch_def<16, 16, 7, 25, 2, true, 1>(bufA, off, wdef + E4, BB(4), bufB);
    // stage 5: (16 -> 8), K=5, 19 -> 15, relu
    launch_off<16, 5, 19, 1, 3, 256>(bufB, wpk + O5, OB(5), off);
    launch_def<16, 8, 5, 19, 1, true, 1>(bufB, off, wdef + E5, BB(5), bufA);
    // stage 6: (8 -> 4), K=3, 15 -> 13, relu
    launch_off<8, 3, 15, 1, 3, 256>(bufA, wpk + O6, OB(6), off);
    launch_def<8, 4, 3, 15, 1, true, 1>(bufA, off, wdef + E6, BB(6), bufB);

    fc8_k<<<64, 256>>>(bufB, fc1w, fc1b, fc2w, fc2b, (float*)d_out);
}

// round 16
// speedup vs baseline: 1.6440x; 1.6440x over previous
#include <cuda_runtime.h>
#include <math.h>

typedef unsigned long long u64;
#define DI __device__ __forceinline__

// ---------------- f32x2 helpers ----------------
DI u64 pack2(float lo, float hi) {
    u64 r; asm("mov.b64 %0, {%1, %2};" : "=l"(r) : "f"(lo), "f"(hi)); return r;
}
DI void unpack2(u64 v, float& lo, float& hi) {
    asm("mov.b64 {%0, %1}, %2;" : "=f"(lo), "=f"(hi) : "l"(v));
}
DI u64 fma2(u64 a, u64 b, u64 c) {
    u64 d; asm("fma.rn.f32x2 %0, %1, %2, %3;" : "=l"(d) : "l"(a), "l"(b), "l"(c));
    return d;
}

// ---------------- scratch ----------------
__device__ float g_bufA[13778944];
__device__ float g_bufB[13778944];
__device__ float g_off [18113536];
__device__ u64   g_wpk [70464];     // off-conv weight pairs, [(c*KK+kk)*OCP+p]
__device__ u64   g_wdef[16800];     // deform weight pairs (transposed)

// off-conv segment bases (u64)
#define O1 0
#define O2 81
#define O3 1377
#define O4 21377
#define O5 59793
#define O6 69793
#define OTOT 70441
// deform segment bases (u64)
#define E1 0
#define E2 72
#define E3 2376
#define E4 8776
#define E5 15048
#define E6 16648
#define ETOT 16792
#define PACK_TOTAL (OTOT + ETOT)

struct PackArgs {
    const float *ow1, *ow2, *ow3, *ow4, *ow5, *ow6;
    const float *ww1, *ww2, *ww3, *ww4, *ww5, *ww6;
};

__global__ void __launch_bounds__(256) pack_all_k(
    PackArgs a, u64* __restrict__ wpk, u64* __restrict__ wdef)
{
    int i = blockIdx.x * 256 + threadIdx.x;
    if (i >= PACK_TOTAL) return;

    if (i < OTOT) {
        auto pw = [&](const float* ow, int base, int OCP, int KK, int CI) {
            int j = i - base;
            int p = j % OCP;
            int t = j / OCP;
            int kk = t % KK, c = t / KK;
            int CIKK = CI * KK;
            wpk[i] = pack2(ow[(2 * p) * CIKK + c * KK + kk],
                           ow[(2 * p + 1) * CIKK + c * KK + kk]);
        };
        if      (i < O2) pw(a.ow1, O1,  9,  9,  1);
        else if (i < O3) pw(a.ow2, O2,  9,  9, 16);
        else if (i < O4) pw(a.ow3, O3, 25, 25, 32);
        else if (i < O5) pw(a.ow4, O4, 49, 49, 16);
        else if (i < O6) pw(a.ow5, O5, 25, 25, 16);
        else             pw(a.ow6, O6,  9,  9,  8);
    } else {
        int e = i - OTOT;
        auto pt = [&](const float* w, int base, int COH, int CI, int KK) {
            int j = e - base; int q = j / COH, ocp = j - q * COH;
            int k = q / CI, c = q - k * CI;
            wdef[e] = pack2(w[((2 * ocp) * CI + c) * KK + k],
                            w[((2 * ocp + 1) * CI + c) * KK + k]);
        };
        if      (e < E2) pt(a.ww1, E1,  8,  1,  9);
        else if (e < E3) pt(a.ww2, E2, 16, 16,  9);
        else if (e < E4) pt(a.ww3, E3,  8, 32, 25);
        else if (e < E5) pt(a.ww4, E4,  8, 16, 49);
        else if (e < E6) pt(a.ww5, E5,  4, 16, 25);
        else             pt(a.ww6, E6,  2,  8,  9);
    }
}

// ---------------- offset conv: PT oc-pairs x 8 px, pipelined weights --------
template<int CI, int K, int H, int SLICES, int PT>
__global__ void __launch_bounds__(256, 2) off_conv_k(
    const float* __restrict__ in, const u64* __restrict__ wpk,
    const float* __restrict__ ob, float* __restrict__ off)
{
    constexpr int W = H, Ho = H - K + 1, Wo = Ho, P = Ho * Wo, HW = H * W;
    constexpr int KK = K * K, OCP = KK;
    constexpr int NT   = (OCP + PT - 1) / PT;
    constexpr int ROWS = (Ho + SLICES - 1) / SLICES;
    constexpr int RIN  = ROWS + K - 1;
    constexpr int QW   = (Wo + 7) / 8;
    constexpr int WP   = (W + 10) & ~3;
    constexpr int NQ   = (K + 10) / 4;

    extern __shared__ float img[];   // CI * WP * RIN
    int b = blockIdx.x;
    int y0 = blockIdx.y * ROWS;
    int rows = min(ROWS, Ho - y0);

    {
        int rin = rows + K - 1;
        const float* inb = in + (long)b * CI * HW + y0 * W;
        int tot = CI * rin * W;
        for (int i = threadIdx.x; i < tot; i += 256) {
            int c  = i / (rin * W);
            int r2 = i - c * rin * W;
            int r  = r2 / W;
            int col = r2 - r * W;
            img[(c * RIN + r) * WP + col] = inb[c * HW + r * W + col];
        }
    }
    __syncthreads();

    float* offb = off + (long)b * (2 * KK) * P;
    int items = NT * rows * QW;

    for (int item = threadIdx.x; item < items; item += 256) {
        int qx = item % QW;
        int t  = item / QW;
        int ly = t % rows;
        int pt = t / rows;
        int x0 = qx * 8;

        int p[PT];
        #pragma unroll
        for (int i = 0; i < PT; i++) p[i] = min(pt * PT + i, OCP - 1);

        u64 acc[PT][8];
        #pragma unroll
        for (int i = 0; i < PT; i++) {
            u64 bini = pack2(__ldg(ob + 2 * p[i]), __ldg(ob + 2 * p[i] + 1));
            #pragma unroll
            for (int j = 0; j < 8; j++) acc[i][j] = bini;
        }

        // pipelined weight stream over flattened (c*KK + kk)
        u64 wv[PT];
        #pragma unroll
        for (int i = 0; i < PT; i++) wv[i] = __ldg(wpk + p[i]);

        #pragma unroll 1
        for (int c = 0; c < CI; c++) {
            const float* s0 = img + (c * RIN + ly) * WP + x0;
            const u64* wc = wpk + (long)c * KK * OCP;
            #pragma unroll
            for (int ky = 0; ky < K; ky++) {
                const float* sr = s0 + ky * WP;
                u64 pv[K + 7];
                #pragma unroll
                for (int q = 0; q < NQ; q++) {
                    float4 f = *reinterpret_cast<const float4*>(sr + 4 * q);
                    if (4 * q     < K + 7) pv[4 * q]     = pack2(f.x, f.x);
                    if (4 * q + 1 < K + 7) pv[4 * q + 1] = pack2(f.y, f.y);
                    if (4 * q + 2 < K + 7) pv[4 * q + 2] = pack2(f.z, f.z);
                    if (4 * q + 3 < K + 7) pv[4 * q + 3] = pack2(f.w, f.w);
                }
                #pragma unroll
                for (int kx = 0; kx < K; kx++) {
                    // prefetch next flat step's weights (valid across c bound;
                    // final over-read stays inside g_wpk)
                    const u64* wn = wc + (ky * K + kx + 1) * OCP;
                    u64 wnx[PT];
                    #pragma unroll
                    for (int i = 0; i < PT; i++) wnx[i] = __ldg(wn + p[i]);
                    #pragma unroll
                    for (int i = 0; i < PT; i++) {
                        #pragma unroll
                        for (int j = 0; j < 8; j++)
                            acc[i][j] = fma2(pv[kx + j], wv[i], acc[i][j]);
                    }
                    #pragma unroll
                    for (int i = 0; i < PT; i++) wv[i] = wnx[i];
                }
            }
        }
        int y = y0 + ly;
        #pragma unroll
        for (int j = 0; j < 8; j++) {
            if (x0 + j < Wo) {
                int po = y * Wo + x0 + j;
                #pragma unroll
                for (int i = 0; i < PT; i++) {
                    float a0, a1; unpack2(acc[i][j], a0, a1);
                    offb[(2 * p[i])     * P + po] = a0;
                    offb[(2 * p[i] + 1) * P + po] = a1;
                }
            }
        }
    }
}

// ---------------- deformable conv, CG channel groups ----------------
template<int CI, int CO, int K, int H, int PIX, bool RELU, int CG>
__global__ void __launch_bounds__(256) deform_k(
    const float* __restrict__ in, const float* __restrict__ off,
    const u64* __restrict__ wt, const float* __restrict__ bias,
    float* __restrict__ out)
{
    constexpr int W = H, Ho = H - K + 1, Wo = Ho, P = Ho * Wo, HW = H * W;
    constexpr int KK = K * K, COH = CO / 2;
    constexpr int NS = KK * CI;
    constexpr int CIG = CI / CG;
    constexpr int WOFF = (CIG * HW + 1) & ~1;

    extern __shared__ float smf[];
    float* img = smf;
    u64* wts = reinterpret_cast<u64*>(smf + WOFF);

    int b = blockIdx.x, tid = threadIdx.x;
    const float* inb = in + (long)b * CI * HW;
    for (int i = tid; i < NS * COH; i += 256) wts[i] = wt[i];

    const float* offb = off + (long)b * (2 * KK) * P;
    float* outb = out + (long)b * CO * P;

    if (CG == 1) {
        for (int i = tid; i < CI * HW; i += 256) img[i] = inb[i];
        __syncthreads();

        for (int p0 = tid; p0 < P; p0 += 256 * PIX) {
            int pp[PIX]; bool pval[PIX]; int yo[PIX], xo[PIX];
            #pragma unroll
            for (int i = 0; i < PIX; i++) {
                int p = p0 + i * 256;
                pval[i] = (p < P);
                p = pval[i] ? p : P - 1;
                pp[i] = p;
                yo[i] = p / Wo;
                xo[i] = p - yo[i] * Wo;
            }

            u64 acc[PIX][COH];
            #pragma unroll
            for (int o = 0; o < COH; o++) {
                u64 bini = pack2(__ldg(bias + 2 * o), __ldg(bias + 2 * o + 1));
                #pragma unroll
                for (int i = 0; i < PIX; i++) acc[i][o] = bini;
            }

            #pragma unroll 1
            for (int ky = 0; ky < K; ky++) {
            #pragma unroll 1
            for (int kx = 0; kx < K; kx++) {
                int k = ky * K + kx;
                int a00[PIX], a01[PIX], a10[PIX], a11[PIX];
                float fya[PIX], fyb[PIX], fxa[PIX], fxb[PIX];
                #pragma unroll
                for (int i = 0; i < PIX; i++) {
                    float oy = __ldg(offb + (2 * k) * P + pp[i]);
                    float ox = __ldg(offb + (2 * k + 1) * P + pp[i]);
                    float py = (float)(ky + yo[i]) + oy;
                    float px = (float)(kx + xo[i]) + ox;
                    float y0f = floorf(py), x0f = floorf(px);
                    float wy = py - y0f, wx = px - x0f;
                    int y0 = (int)y0f, x0 = (int)x0f;
                    fya[i] = (y0 >= 0 && y0 < H)      ? (1.f - wy) : 0.f;
                    fyb[i] = (y0 >= -1 && y0 < H - 1) ? wy : 0.f;
                    fxa[i] = (x0 >= 0 && x0 < W)      ? (1.f - wx) : 0.f;
                    fxb[i] = (x0 >= -1 && x0 < W - 1) ? wx : 0.f;
                    int y0c = min(max(y0, 0), H - 1);
                    int y1c = min(max(y0 + 1, 0), H - 1);
                    int x0c = min(max(x0, 0), W - 1);
                    int x1c = min(max(x0 + 1, 0), W - 1);
                    a00[i] = y0c * W + x0c; a01[i] = y0c * W + x1c;
                    a10[i] = y1c * W + x0c; a11[i] = y1c * W + x1c;
                }
                const u64* wrow = wts + k * CI * COH;
                #pragma unroll 2
                for (int c = 0; c < CI; c++) {
                    const float* ic = img + c * HW;
                    u64 ss[PIX];
                    #pragma unroll
                    for (int i = 0; i < PIX; i++) {
                        float t0 = ic[a00[i]] * fxa[i] + ic[a01[i]] * fxb[i];
                        float t1 = ic[a10[i]] * fxa[i] + ic[a11[i]] * fxb[i];
                        float s  = t0 * fya[i] + t1 * fyb[i];
                        ss[i] = pack2(s, s);
                    }
                    const u64* wc = wrow + c * COH;
                    #pragma unroll
                    for (int o = 0; o < COH; o++) {
                        u64 wv = wc[o];
                        #pragma unroll
                        for (int i = 0; i < PIX; i++)
                            acc[i][o] = fma2(ss[i], wv, acc[i][o]);
                    }
                }
            }}

            #pragma unroll
            for (int i = 0; i < PIX; i++) if (pval[i]) {
                #pragma unroll
                for (int o = 0; o < COH; o++) {
                    float a0, a1; unpack2(acc[i][o], a0, a1);
                    if (RELU) { a0 = fmaxf(a0, 0.f); a1 = fmaxf(a1, 0.f); }
                    outb[(2 * o) * P + pp[i]]     = a0;
                    outb[(2 * o + 1) * P + pp[i]] = a1;
                }
            }
        }
    } else {
        static_assert(CG == 1 || 256 * PIX >= P, "PIX must cover P");
        int pp[PIX]; bool pval[PIX]; int yo[PIX], xo[PIX];
        #pragma unroll
        for (int i = 0; i < PIX; i++) {
            int p = tid + i * 256;
            pval[i] = (p < P);
            p = pval[i] ? p : P - 1;
            pp[i] = p;
            yo[i] = p / Wo;
            xo[i] = p - yo[i] * Wo;
        }

        u64 acc[PIX][COH];
        #pragma unroll
        for (int o = 0; o < COH; o++) {
            u64 bini = pack2(__ldg(bias + 2 * o), __ldg(bias + 2 * o + 1));
            #pragma unroll
            for (int i = 0; i < PIX; i++) acc[i][o] = bini;
        }

        #pragma unroll 1
        for (int g = 0; g < CG; g++) {
            if (g > 0) __syncthreads();
            const float* src = inb + g * CIG * HW;
            for (int i = tid; i < CIG * HW; i += 256) img[i] = src[i];
            __syncthreads();

            #pragma unroll 1
            for (int ky = 0; ky < K; ky++) {
            #pragma unroll 1
            for (int kx = 0; kx < K; kx++) {
                int k = ky * K + kx;
                int a00[PIX], a01[PIX], a10[PIX], a11[PIX];
                float fya[PIX], fyb[PIX], fxa[PIX], fxb[PIX];
                #pragma unroll
                for (int i = 0; i < PIX; i++) {
                    float oy = __ldg(offb + (2 * k) * P + pp[i]);
                    float ox = __ldg(offb + (2 * k + 1) * P + pp[i]);
                    float py = (float)(ky + yo[i]) + oy;
                    float px = (float)(kx + xo[i]) + ox;
                    float y0f = floorf(py), x0f = floorf(px);
                    float wy = py - y0f, wx = px - x0f;
                    int y0 = (int)y0f, x0 = (int)x0f;
                    fya[i] = (y0 >= 0 && y0 < H)      ? (1.f - wy) : 0.f;
                    fyb[i] = (y0 >= -1 && y0 < H - 1) ? wy : 0.f;
                    fxa[i] = (x0 >= 0 && x0 < W)      ? (1.f - wx) : 0.f;
                    fxb[i] = (x0 >= -1 && x0 < W - 1) ? wx : 0.f;
                    int y0c = min(max(y0, 0), H - 1);
                    int y1c = min(max(y0 + 1, 0), H - 1);
                    int x0c = min(max(x0, 0), W - 1);
                    int x1c = min(max(x0 + 1, 0), W - 1);
                    a00[i] = y0c * W + x0c; a01[i] = y0c * W + x1c;
                    a10[i] = y1c * W + x0c; a11[i] = y1c * W + x1c;
                }
                #pragma unroll 2
                for (int cl = 0; cl < CIG; cl++) {
                    const float* ic = img + cl * HW;
                    u64 ss[PIX];
                    #pragma unroll
                    for (int i = 0; i < PIX; i++) {
                        float t0 = ic[a00[i]] * fxa[i] + ic[a01[i]] * fxb[i];
                        float t1 = ic[a10[i]] * fxa[i] + ic[a11[i]] * fxb[i];
                        float s  = t0 * fya[i] + t1 * fyb[i];
                        ss[i] = pack2(s, s);
                    }
                    const u64* wc = wts + (k * CI + g * CIG + cl) * COH;
                    #pragma unroll
                    for (int o = 0; o < COH; o++) {
                        u64 wv = wc[o];
                        #pragma unroll
                        for (int i = 0; i < PIX; i++)
                            acc[i][o] = fma2(ss[i], wv, acc[i][o]);
                    }
                }
            }}
        }

        #pragma unroll
        for (int i = 0; i < PIX; i++) if (pval[i]) {
            #pragma unroll
            for (int o = 0; o < COH; o++) {
                float a0, a1; unpack2(acc[i][o], a0, a1);
                if (RELU) { a0 = fmaxf(a0, 0.f); a1 = fmaxf(a1, 0.f); }
                outb[(2 * o) * P + pp[i]]     = a0;
                outb[(2 * o + 1) * P + pp[i]] = a1;
            }
        }
    }
}

// ---------------- batched FC: 4 batch rows per block ----------------
__global__ void __launch_bounds__(256) fc4_k(
    const float* __restrict__ h, const float* __restrict__ w1,
    const float* __restrict__ b1, const float* __restrict__ w2,
    const float* __restrict__ b2, float* __restrict__ out)
{
    __shared__ float flat[4][676];
    __shared__ float z[4][256];
    int b0 = blockIdx.x * 4, tid = threadIdx.x;
    int lane = tid & 31, wid = tid >> 5;

    for (int i = tid; i < 4 * 676; i += 256) {
        int r = i / 676, c = i - r * 676;
        flat[r][c] = h[(long)(b0 + r) * 676 + c];
    }
    __syncthreads();

    for (int oc = wid; oc < 256; oc += 8) {
        float acc0 = 0.f, acc1 = 0.f, acc2 = 0.f, acc3 = 0.f;
        const float* wr = w1 + (long)oc * 676;
        for (int i = lane; i < 676; i += 32) {
            float w = wr[i];
            acc0 += flat[0][i] * w;
            acc1 += flat[1][i] * w;
            acc2 += flat[2][i] * w;
            acc3 += flat[3][i] * w;
        }
        #pragma unroll
        for (int s = 16; s; s >>= 1) {
            acc0 += __shfl_down_sync(0xffffffffu, acc0, s);
            acc1 += __shfl_down_sync(0xffffffffu, acc1, s);
            acc2 += __shfl_down_sync(0xffffffffu, acc2, s);
            acc3 += __shfl_down_sync(0xffffffffu, acc3, s);
        }
        if (lane == 0) {
            float bb = b1[oc];
            z[0][oc] = fmaxf(acc0 + bb, 0.f);
            z[1][oc] = fmaxf(acc1 + bb, 0.f);
            z[2][oc] = fmaxf(acc2 + bb, 0.f);
            z[3][oc] = fmaxf(acc3 + bb, 0.f);
        }
    }
    __syncthreads();

    for (int oc = wid; oc < 10; oc += 8) {
        float acc0 = 0.f, acc1 = 0.f, acc2 = 0.f, acc3 = 0.f;
        const float* wr = w2 + (long)oc * 256;
        for (int i = lane; i < 256; i += 32) {
            float w = wr[i];
            acc0 += z[0][i] * w;
            acc1 += z[1][i] * w;
            acc2 += z[2][i] * w;
            acc3 += z[3][i] * w;
        }
        #pragma unroll
        for (int s = 16; s; s >>= 1) {
            acc0 += __shfl_down_sync(0xffffffffu, acc0, s);
            acc1 += __shfl_down_sync(0xffffffffu, acc1, s);
            acc2 += __shfl_down_sync(0xffffffffu, acc2, s);
            acc3 += __shfl_down_sync(0xffffffffu, acc3, s);
        }
        if (lane == 0) {
            float bb = b2[oc];
            out[(long)(b0 + 0) * 10 + oc] = acc0 + bb;
            out[(long)(b0 + 1) * 10 + oc] = acc1 + bb;
            out[(long)(b0 + 2) * 10 + oc] = acc2 + bb;
            out[(long)(b0 + 3) * 10 + oc] = acc3 + bb;
        }
    }
}

// ---------------- host ----------------
template<int CI, int K, int H, int SLICES, int PT>
static void launch_off(const float* in, const u64* wpk, const float* ob, float* off)
{
    constexpr int Ho = H - K + 1;
    constexpr int ROWS = (Ho + SLICES - 1) / SLICES;
    constexpr int RIN = ROWS + K - 1;
    constexpr int WP = (H + 10) & ~3;
    constexpr int SM = CI * WP * RIN * 4;
    cudaFuncSetAttribute(off_conv_k<CI, K, H, SLICES, PT>,
                         cudaFuncAttributeMaxDynamicSharedMemorySize, SM);
    off_conv_k<CI, K, H, SLICES, PT><<<dim3(512, SLICES), 256, SM>>>(in, wpk, ob, off);
}

template<int CI, int CO, int K, int H, int PIX, bool RELU, int CG>
static void launch_def(const float* in, const float* off, const u64* wt,
                       const float* bias, float* out)
{
    constexpr int CIG = CI / CG;
    constexpr int WOFF = (CIG * H * H + 1) & ~1;
    constexpr int SM = WOFF * 4 + K * K * CI * (CO / 2) * 8;
    cudaFuncSetAttribute(deform_k<CI, CO, K, H, PIX, RELU, CG>,
                         cudaFuncAttributeMaxDynamicSharedMemorySize, SM);
    deform_k<CI, CO, K, H, PIX, RELU, CG><<<512, 256, SM>>>(in, off, wt, bias, out);
}

extern "C" void kernel_launch(void* const* d_in, const int* in_sizes, int n_in,
                              void* d_out, int out_size)
{
    (void)in_sizes; (void)n_in; (void)out_size;
    const float* x = (const float*)d_in[0];
    auto OW = [&](int i) { return (const float*)d_in[4 * i - 3]; };
    auto OB = [&](int i) { return (const float*)d_in[4 * i - 2]; };
    auto WW = [&](int i) { return (const float*)d_in[4 * i - 1]; };
    auto BB = [&](int i) { return (const float*)d_in[4 * i]; };
    const float* fc1w = (const float*)d_in[25];
    const float* fc1b = (const float*)d_in[26];
    const float* fc2w = (const float*)d_in[27];
    const float* fc2b = (const float*)d_in[28];

    float *bufA, *bufB, *off;
    u64 *wpk, *wdef;
    cudaGetSymbolAddress((void**)&bufA, g_bufA);
    cudaGetSymbolAddress((void**)&bufB, g_bufB);
    cudaGetSymbolAddress((void**)&off,  g_off);
    cudaGetSymbolAddress((void**)&wpk,  g_wpk);
    cudaGetSymbolAddress((void**)&wdef, g_wdef);

    PackArgs pa = { OW(1), OW(2), OW(3), OW(4), OW(5), OW(6),
                    WW(1), WW(2), WW(3), WW(4), WW(5), WW(6) };
    pack_all_k<<<(PACK_TOTAL + 255) / 256, 256>>>(pa, wpk, wdef);

    // stage 1: (1 -> 16), K=3, 33 -> 31, relu
    launch_off<1, 3, 33, 1, 3>(x, wpk + O1, OB(1), off);
    launch_def<1, 16, 3, 33, 4, true, 1>(x, off, wdef + E1, BB(1), bufA);
    // stage 2: (16 -> 32), K=3, 31 -> 29, relu
    launch_off<16, 3, 31, 1, 3>(bufA, wpk + O2, OB(2), off);
    launch_def<16, 32, 3, 31, 2, true, 1>(bufA, off, wdef + E2, BB(2), bufB);
    // stage 3: (32 -> 16), K=5, 29 -> 25, no relu  (image in 2 channel halves)
    launch_off<32, 5, 29, 2, 3>(bufB, wpk + O3, OB(3), off);
    launch_def<32, 16, 5, 29, 3, false, 2>(bufB, off, wdef + E3, BB(3), bufA);
    // stage 4: (16 -> 16), K=7, 25 -> 19, relu
    launch_off<16, 7, 25, 2, 3>(bufA, wpk + O4, OB(4), off);
    launch_def<16, 16, 7, 25, 2, true, 1>(bufA, off, wdef + E4, BB(4), bufB);
    // stage 5: (16 -> 8), K=5, 19 -> 15, relu
    launch_off<16, 5, 19, 1, 3>(bufB, wpk + O5, OB(5), off);
    launch_def<16, 8, 5, 19, 1, true, 1>(bufB, off, wdef + E5, BB(5), bufA);
    // stage 6: (8 -> 4), K=3, 15 -> 13, relu
    launch_off<8, 3, 15, 1, 3>(bufA, wpk + O6, OB(6), off);
    launch_def<8, 4, 3, 15, 1, true, 1>(bufA, off, wdef + E6, BB(6), bufB);

    fc4_k<<<128, 256>>>(bufB, fc1w, fc1b, fc2w, fc2b, (float*)d_out);
}

// round 17
// speedup vs baseline: 1.6996x; 1.0338x over previous
#include <cuda_runtime.h>
#include <math.h>

typedef unsigned long long u64;
#define DI __device__ __forceinline__

// ---------------- f32x2 helpers ----------------
DI u64 pack2(float lo, float hi) {
    u64 r; asm("mov.b64 %0, {%1, %2};" : "=l"(r) : "f"(lo), "f"(hi)); return r;
}
DI void unpack2(u64 v, float& lo, float& hi) {
    asm("mov.b64 {%0, %1}, %2;" : "=f"(lo), "=f"(hi) : "l"(v));
}
DI u64 fma2(u64 a, u64 b, u64 c) {
    u64 d; asm("fma.rn.f32x2 %0, %1, %2, %3;" : "=l"(d) : "l"(a), "l"(b), "l"(c));
    return d;
}

// ---------------- scratch ----------------
__device__ float g_bufA[13778944];
__device__ float g_bufB[13778944];
__device__ u64   g_off [9056768];   // offset pairs (oy,ox) per (k, pixel)
__device__ u64   g_wpk [70464];     // off-conv weight pairs, [(c*KK+kk)*OCP+p]
__device__ u64   g_wdef[16800];     // deform weight pairs (transposed)

// off-conv segment bases (u64)
#define O1 0
#define O2 81
#define O3 1377
#define O4 21377
#define O5 59793
#define O6 69793
#define OTOT 70441
// deform segment bases (u64)
#define E1 0
#define E2 72
#define E3 2376
#define E4 8776
#define E5 15048
#define E6 16648
#define ETOT 16792
#define PACK_TOTAL (OTOT + ETOT)

struct PackArgs {
    const float *ow1, *ow2, *ow3, *ow4, *ow5, *ow6;
    const float *ww1, *ww2, *ww3, *ww4, *ww5, *ww6;
};

__global__ void __launch_bounds__(256) pack_all_k(
    PackArgs a, u64* __restrict__ wpk, u64* __restrict__ wdef)
{
    int i = blockIdx.x * 256 + threadIdx.x;
    if (i >= PACK_TOTAL) return;

    if (i < OTOT) {
        auto pw = [&](const float* ow, int base, int OCP, int KK, int CI) {
            int j = i - base;
            int p = j % OCP;
            int t = j / OCP;
            int kk = t % KK, c = t / KK;
            int CIKK = CI * KK;
            wpk[i] = pack2(ow[(2 * p) * CIKK + c * KK + kk],
                           ow[(2 * p + 1) * CIKK + c * KK + kk]);
        };
        if      (i < O2) pw(a.ow1, O1,  9,  9,  1);
        else if (i < O3) pw(a.ow2, O2,  9,  9, 16);
        else if (i < O4) pw(a.ow3, O3, 25, 25, 32);
        else if (i < O5) pw(a.ow4, O4, 49, 49, 16);
        else if (i < O6) pw(a.ow5, O5, 25, 25, 16);
        else             pw(a.ow6, O6,  9,  9,  8);
    } else {
        int e = i - OTOT;
        auto pt = [&](const float* w, int base, int COH, int CI, int KK) {
            int j = e - base; int q = j / COH, ocp = j - q * COH;
            int k = q / CI, c = q - k * CI;
            wdef[e] = pack2(w[((2 * ocp) * CI + c) * KK + k],
                            w[((2 * ocp + 1) * CI + c) * KK + k]);
        };
        if      (e < E2) pt(a.ww1, E1,  8,  1,  9);
        else if (e < E3) pt(a.ww2, E2, 16, 16,  9);
        else if (e < E4) pt(a.ww3, E3,  8, 32, 25);
        else if (e < E5) pt(a.ww4, E4,  8, 16, 49);
        else if (e < E6) pt(a.ww5, E5,  4, 16, 25);
        else             pt(a.ww6, E6,  2,  8,  9);
    }
}

// ---------------- offset conv: PT oc-pairs x 8 px, pipelined weights --------
// Output: u64 (oy,ox) pair per (k, pixel): off[b*KK*P + k*P + px].
template<int CI, int K, int H, int SLICES, int PT>
__global__ void __launch_bounds__(256, 2) off_conv_k(
    const float* __restrict__ in, const u64* __restrict__ wpk,
    const float* __restrict__ ob, u64* __restrict__ off)
{
    constexpr int W = H, Ho = H - K + 1, Wo = Ho, P = Ho * Wo, HW = H * W;
    constexpr int KK = K * K, OCP = KK;
    constexpr int NT   = (OCP + PT - 1) / PT;
    constexpr int ROWS = (Ho + SLICES - 1) / SLICES;
    constexpr int RIN  = ROWS + K - 1;
    constexpr int QW   = (Wo + 7) / 8;
    constexpr int WP   = (W + 10) & ~3;
    constexpr int NQ   = (K + 10) / 4;

    extern __shared__ float img[];   // CI * WP * RIN
    int b = blockIdx.x;
    int y0 = blockIdx.y * ROWS;
    int rows = min(ROWS, Ho - y0);

    {
        int rin = rows + K - 1;
        const float* inb = in + (long)b * CI * HW + y0 * W;
        int tot = CI * rin * W;
        for (int i = threadIdx.x; i < tot; i += 256) {
            int c  = i / (rin * W);
            int r2 = i - c * rin * W;
            int r  = r2 / W;
            int col = r2 - r * W;
            img[(c * RIN + r) * WP + col] = inb[c * HW + r * W + col];
        }
    }
    __syncthreads();

    u64* offb = off + (long)b * KK * P;
    int items = NT * rows * QW;

    for (int item = threadIdx.x; item < items; item += 256) {
        int qx = item % QW;
        int t  = item / QW;
        int ly = t % rows;
        int pt = t / rows;
        int x0 = qx * 8;

        int p[PT];
        #pragma unroll
        for (int i = 0; i < PT; i++) p[i] = min(pt * PT + i, OCP - 1);

        u64 acc[PT][8];
        #pragma unroll
        for (int i = 0; i < PT; i++) {
            u64 bini = pack2(__ldg(ob + 2 * p[i]), __ldg(ob + 2 * p[i] + 1));
            #pragma unroll
            for (int j = 0; j < 8; j++) acc[i][j] = bini;
        }

        // pipelined weight stream over flattened (c*KK + kk)
        u64 wv[PT];
        #pragma unroll
        for (int i = 0; i < PT; i++) wv[i] = __ldg(wpk + p[i]);

        #pragma unroll 1
        for (int c = 0; c < CI; c++) {
            const float* s0 = img + (c * RIN + ly) * WP + x0;
            const u64* wc = wpk + (long)c * KK * OCP;
            #pragma unroll
            for (int ky = 0; ky < K; ky++) {
                const float* sr = s0 + ky * WP;
                u64 pv[K + 7];
                #pragma unroll
                for (int q = 0; q < NQ; q++) {
                    float4 f = *reinterpret_cast<const float4*>(sr + 4 * q);
                    if (4 * q     < K + 7) pv[4 * q]     = pack2(f.x, f.x);
                    if (4 * q + 1 < K + 7) pv[4 * q + 1] = pack2(f.y, f.y);
                    if (4 * q + 2 < K + 7) pv[4 * q + 2] = pack2(f.z, f.z);
                    if (4 * q + 3 < K + 7) pv[4 * q + 3] = pack2(f.w, f.w);
                }
                #pragma unroll
                for (int kx = 0; kx < K; kx++) {
                    // prefetch next flat step's weights (valid across c bound;
                    // final over-read stays inside g_wpk)
                    const u64* wn = wc + (ky * K + kx + 1) * OCP;
                    u64 wnx[PT];
                    #pragma unroll
                    for (int i = 0; i < PT; i++) wnx[i] = __ldg(wn + p[i]);
                    #pragma unroll
                    for (int i = 0; i < PT; i++) {
                        #pragma unroll
                        for (int j = 0; j < 8; j++)
                            acc[i][j] = fma2(pv[kx + j], wv[i], acc[i][j]);
                    }
                    #pragma unroll
                    for (int i = 0; i < PT; i++) wv[i] = wnx[i];
                }
            }
        }
        int y = y0 + ly;
        #pragma unroll
        for (int j = 0; j < 8; j++) {
            if (x0 + j < Wo) {
                int po = y * Wo + x0 + j;
                #pragma unroll
                for (int i = 0; i < PT; i++)
                    offb[(long)p[i] * P + po] = acc[i][j];   // (oy, ox) pair
            }
        }
    }
}

// ---------------- deformable conv, CG channel groups ----------------
// Offsets: u64 (oy,ox) per (k,pixel). Weights: SMEM ulonglong2 (LDS.128).
template<int CI, int CO, int K, int H, int PIX, bool RELU, int CG>
__global__ void __launch_bounds__(256) deform_k(
    const float* __restrict__ in, const u64* __restrict__ off,
    const u64* __restrict__ wt, const float* __restrict__ bias,
    float* __restrict__ out)
{
    constexpr int W = H, Ho = H - K + 1, Wo = Ho, P = Ho * Wo, HW = H * W;
    constexpr int KK = K * K, COH = CO / 2;
    constexpr int NS = KK * CI;
    constexpr int CIG = CI / CG;
    constexpr int WOFF = (CIG * HW + 3) & ~3;   // 16B-align weight area

    extern __shared__ float smf[];
    float* img = smf;
    u64* wts = reinterpret_cast<u64*>(smf + WOFF);

    int b = blockIdx.x, tid = threadIdx.x;
    const float* inb = in + (long)b * CI * HW;
    for (int i = tid; i < NS * COH; i += 256) wts[i] = wt[i];

    const u64* offb = off + (long)b * KK * P;
    float* outb = out + (long)b * CO * P;

    if (CG == 1) {
        for (int i = tid; i < CI * HW; i += 256) img[i] = inb[i];
        __syncthreads();

        for (int p0 = tid; p0 < P; p0 += 256 * PIX) {
            int pp[PIX]; bool pval[PIX]; int yo[PIX], xo[PIX];
            #pragma unroll
            for (int i = 0; i < PIX; i++) {
                int p = p0 + i * 256;
                pval[i] = (p < P);
                p = pval[i] ? p : P - 1;
                pp[i] = p;
                yo[i] = p / Wo;
                xo[i] = p - yo[i] * Wo;
            }

            u64 acc[PIX][COH];
            #pragma unroll
            for (int o = 0; o < COH; o++) {
                u64 bini = pack2(__ldg(bias + 2 * o), __ldg(bias + 2 * o + 1));
                #pragma unroll
                for (int i = 0; i < PIX; i++) acc[i][o] = bini;
            }

            #pragma unroll 1
            for (int ky = 0; ky < K; ky++) {
            #pragma unroll 1
            for (int kx = 0; kx < K; kx++) {
                int k = ky * K + kx;
                int a00[PIX], a01[PIX], a10[PIX], a11[PIX];
                float fya[PIX], fyb[PIX], fxa[PIX], fxb[PIX];
                #pragma unroll
                for (int i = 0; i < PIX; i++) {
                    float2 ov = __ldg(reinterpret_cast<const float2*>(
                                          offb + (long)k * P + pp[i]));
                    float py = (float)(ky + yo[i]) + ov.x;
                    float px = (float)(kx + xo[i]) + ov.y;
                    float y0f = floorf(py), x0f = floorf(px);
                    float wy = py - y0f, wx = px - x0f;
                    int y0 = (int)y0f, x0 = (int)x0f;
                    fya[i] = (y0 >= 0 && y0 < H)      ? (1.f - wy) : 0.f;
                    fyb[i] = (y0 >= -1 && y0 < H - 1) ? wy : 0.f;
                    fxa[i] = (x0 >= 0 && x0 < W)      ? (1.f - wx) : 0.f;
                    fxb[i] = (x0 >= -1 && x0 < W - 1) ? wx : 0.f;
                    int y0c = min(max(y0, 0), H - 1);
                    int y1c = min(max(y0 + 1, 0), H - 1);
                    int x0c = min(max(x0, 0), W - 1);
                    int x1c = min(max(x0 + 1, 0), W - 1);
                    a00[i] = y0c * W + x0c; a01[i] = y0c * W + x1c;
                    a10[i] = y1c * W + x0c; a11[i] = y1c * W + x1c;
                }
                const u64* wrow = wts + k * CI * COH;
                #pragma unroll 2
                for (int c = 0; c < CI; c++) {
                    const float* ic = img + c * HW;
                    u64 ss[PIX];
                    #pragma unroll
                    for (int i = 0; i < PIX; i++) {
                        float t0 = ic[a00[i]] * fxa[i] + ic[a01[i]] * fxb[i];
                        float t1 = ic[a10[i]] * fxa[i] + ic[a11[i]] * fxb[i];
                        float s  = t0 * fya[i] + t1 * fyb[i];
                        ss[i] = pack2(s, s);
                    }
                    const ulonglong2* wc2 =
                        reinterpret_cast<const ulonglong2*>(wrow + c * COH);
                    #pragma unroll
                    for (int o2 = 0; o2 < COH / 2; o2++) {
                        ulonglong2 wv2 = wc2[o2];
                        #pragma unroll
                        for (int i = 0; i < PIX; i++) {
                            acc[i][2 * o2]     = fma2(ss[i], wv2.x, acc[i][2 * o2]);
                            acc[i][2 * o2 + 1] = fma2(ss[i], wv2.y, acc[i][2 * o2 + 1]);
                        }
                    }
                }
            }}

            #pragma unroll
            for (int i = 0; i < PIX; i++) if (pval[i]) {
                #pragma unroll
                for (int o = 0; o < COH; o++) {
                    float a0, a1; unpack2(acc[i][o], a0, a1);
                    if (RELU) { a0 = fmaxf(a0, 0.f); a1 = fmaxf(a1, 0.f); }
                    outb[(2 * o) * P + pp[i]]     = a0;
                    outb[(2 * o + 1) * P + pp[i]] = a1;
                }
            }
        }
    } else {
        static_assert(CG == 1 || 256 * PIX >= P, "PIX must cover P");
        int pp[PIX]; bool pval[PIX]; int yo[PIX], xo[PIX];
        #pragma unroll
        for (int i = 0; i < PIX; i++) {
            int p = tid + i * 256;
            pval[i] = (p < P);
            p = pval[i] ? p : P - 1;
            pp[i] = p;
            yo[i] = p / Wo;
            xo[i] = p - yo[i] * Wo;
        }

        u64 acc[PIX][COH];
        #pragma unroll
        for (int o = 0; o < COH; o++) {
            u64 bini = pack2(__ldg(bias + 2 * o), __ldg(bias + 2 * o + 1));
            #pragma unroll
            for (int i = 0; i < PIX; i++) acc[i][o] = bini;
        }

        #pragma unroll 1
        for (int g = 0; g < CG; g++) {
            if (g > 0) __syncthreads();
            const float* src = inb + g * CIG * HW;
            for (int i = tid; i < CIG * HW; i += 256) img[i] = src[i];
            __syncthreads();

            #pragma unroll 1
            for (int ky = 0; ky < K; ky++) {
            #pragma unroll 1
            for (int kx = 0; kx < K; kx++) {
                int k = ky * K + kx;
                int a00[PIX], a01[PIX], a10[PIX], a11[PIX];
                float fya[PIX], fyb[PIX], fxa[PIX], fxb[PIX];
                #pragma unroll
                for (int i = 0; i < PIX; i++) {
                    float2 ov = __ldg(reinterpret_cast<const float2*>(
                                          offb + (long)k * P + pp[i]));
                    float py = (float)(ky + yo[i]) + ov.x;
                    float px = (float)(kx + xo[i]) + ov.y;
                    float y0f = floorf(py), x0f = floorf(px);
                    float wy = py - y0f, wx = px - x0f;
                    int y0 = (int)y0f, x0 = (int)x0f;
                    fya[i] = (y0 >= 0 && y0 < H)      ? (1.f - wy) : 0.f;
                    fyb[i] = (y0 >= -1 && y0 < H - 1) ? wy : 0.f;
                    fxa[i] = (x0 >= 0 && x0 < W)      ? (1.f - wx) : 0.f;
                    fxb[i] = (x0 >= -1 && x0 < W - 1) ? wx : 0.f;
                    int y0c = min(max(y0, 0), H - 1);
                    int y1c = min(max(y0 + 1, 0), H - 1);
                    int x0c = min(max(x0, 0), W - 1);
                    int x1c = min(max(x0 + 1, 0), W - 1);
                    a00[i] = y0c * W + x0c; a01[i] = y0c * W + x1c;
                    a10[i] = y1c * W + x0c; a11[i] = y1c * W + x1c;
                }
                #pragma unroll 2
                for (int cl = 0; cl < CIG; cl++) {
                    const float* ic = img + cl * HW;
                    u64 ss[PIX];
                    #pragma unroll
                    for (int i = 0; i < PIX; i++) {
                        float t0 = ic[a00[i]] * fxa[i] + ic[a01[i]] * fxb[i];
                        float t1 = ic[a10[i]] * fxa[i] + ic[a11[i]] * fxb[i];
                        float s  = t0 * fya[i] + t1 * fyb[i];
                        ss[i] = pack2(s, s);
                    }
                    const ulonglong2* wc2 = reinterpret_cast<const ulonglong2*>(
                        wts + (k * CI + g * CIG + cl) * COH);
                    #pragma unroll
                    for (int o2 = 0; o2 < COH / 2; o2++) {
                        ulonglong2 wv2 = wc2[o2];
                        #pragma unroll
                        for (int i = 0; i < PIX; i++) {
                            acc[i][2 * o2]     = fma2(ss[i], wv2.x, acc[i][2 * o2]);
                            acc[i][2 * o2 + 1] = fma2(ss[i], wv2.y, acc[i][2 * o2 + 1]);
                        }
                    }
                }
            }}
        }

        #pragma unroll
        for (int i = 0; i < PIX; i++) if (pval[i]) {
            #pragma unroll
            for (int o = 0; o < COH; o++) {
                float a0, a1; unpack2(acc[i][o], a0, a1);
                if (RELU) { a0 = fmaxf(a0, 0.f); a1 = fmaxf(a1, 0.f); }
                outb[(2 * o) * P + pp[i]]     = a0;
                outb[(2 * o + 1) * P + pp[i]] = a1;
            }
        }
    }
}

// ---------------- batched FC: 4 batch rows per block ----------------
__global__ void __launch_bounds__(256) fc4_k(
    const float* __restrict__ h, const float* __restrict__ w1,
    const float* __restrict__ b1, const float* __restrict__ w2,
    const float* __restrict__ b2, float* __restrict__ out)
{
    __shared__ float flat[4][676];
    __shared__ float z[4][256];
    int b0 = blockIdx.x * 4, tid = threadIdx.x;
    int lane = tid & 31, wid = tid >> 5;

    for (int i = tid; i < 4 * 676; i += 256) {
        int r = i / 676, c = i - r * 676;
        flat[r][c] = h[(long)(b0 + r) * 676 + c];
    }
    __syncthreads();

    for (int oc = wid; oc < 256; oc += 8) {
        float acc0 = 0.f, acc1 = 0.f, acc2 = 0.f, acc3 = 0.f;
        const float* wr = w1 + (long)oc * 676;
        for (int i = lane; i < 676; i += 32) {
            float w = wr[i];
            acc0 += flat[0][i] * w;
            acc1 += flat[1][i] * w;
            acc2 += flat[2][i] * w;
            acc3 += flat[3][i] * w;
        }
        #pragma unroll
        for (int s = 16; s; s >>= 1) {
            acc0 += __shfl_down_sync(0xffffffffu, acc0, s);
            acc1 += __shfl_down_sync(0xffffffffu, acc1, s);
            acc2 += __shfl_down_sync(0xffffffffu, acc2, s);
            acc3 += __shfl_down_sync(0xffffffffu, acc3, s);
        }
        if (lane == 0) {
            float bb = b1[oc];
            z[0][oc] = fmaxf(acc0 + bb, 0.f);
            z[1][oc] = fmaxf(acc1 + bb, 0.f);
            z[2][oc] = fmaxf(acc2 + bb, 0.f);
            z[3][oc] = fmaxf(acc3 + bb, 0.f);
        }
    }
    __syncthreads();

    for (int oc = wid; oc < 10; oc += 8) {
        float acc0 = 0.f, acc1 = 0.f, acc2 = 0.f, acc3 = 0.f;
        const float* wr = w2 + (long)oc * 256;
        for (int i = lane; i < 256; i += 32) {
            float w = wr[i];
            acc0 += z[0][i] * w;
            acc1 += z[1][i] * w;
            acc2 += z[2][i] * w;
            acc3 += z[3][i] * w;
        }
        #pragma unroll
        for (int s = 16; s; s >>= 1) {
            acc0 += __shfl_down_sync(0xffffffffu, acc0, s);
            acc1 += __shfl_down_sync(0xffffffffu, acc1, s);
            acc2 += __shfl_down_sync(0xffffffffu, acc2, s);
            acc3 += __shfl_down_sync(0xffffffffu, acc3, s);
        }
        if (lane == 0) {
            float bb = b2[oc];
            out[(long)(b0 + 0) * 10 + oc] = acc0 + bb;
            out[(long)(b0 + 1) * 10 + oc] = acc1 + bb;
            out[(long)(b0 + 2) * 10 + oc] = acc2 + bb;
            out[(long)(b0 + 3) * 10 + oc] = acc3 + bb;
        }
    }
}

// ---------------- host ----------------
template<int CI, int K, int H, int SLICES, int PT>
static void launch_off(const float* in, const u64* wpk, const float* ob, u64* off)
{
    constexpr int Ho = H - K + 1;
    constexpr int ROWS = (Ho + SLICES - 1) / SLICES;
    constexpr int RIN = ROWS + K - 1;
    constexpr int WP = (H + 10) & ~3;
    constexpr int SM = CI * WP * RIN * 4;
    cudaFuncSetAttribute(off_conv_k<CI, K, H, SLICES, PT>,
                         cudaFuncAttributeMaxDynamicSharedMemorySize, SM);
    off_conv_k<CI, K, H, SLICES, PT><<<dim3(512, SLICES), 256, SM>>>(in, wpk, ob, off);
}

template<int CI, int CO, int K, int H, int PIX, bool RELU, int CG>
static void launch_def(const float* in, const u64* off, const u64* wt,
                       const float* bias, float* out)
{
    constexpr int CIG = CI / CG;
    constexpr int WOFF = (CIG * H * H + 3) & ~3;
    constexpr int SM = WOFF * 4 + K * K * CI * (CO / 2) * 8;
    cudaFuncSetAttribute(deform_k<CI, CO, K, H, PIX, RELU, CG>,
                         cudaFuncAttributeMaxDynamicSharedMemorySize, SM);
    deform_k<CI, CO, K, H, PIX, RELU, CG><<<512, 256, SM>>>(in, off, wt, bias, out);
}

extern "C" void kernel_launch(void* const* d_in, const int* in_sizes, int n_in,
                              void* d_out, int out_size)
{
    (void)in_sizes; (void)n_in; (void)out_size;
    const float* x = (const float*)d_in[0];
    auto OW = [&](int i) { return (const float*)d_in[4 * i - 3]; };
    auto OB = [&](int i) { return (const float*)d_in[4 * i - 2]; };
    auto WW = [&](int i) { return (const float*)d_in[4 * i - 1]; };
    auto BB = [&](int i) { return (const float*)d_in[4 * i]; };
    const float* fc1w = (const float*)d_in[25];
    const float* fc1b = (const float*)d_in[26];
    const float* fc2w = (const float*)d_in[27];
    const float* fc2b = (const float*)d_in[28];

    float *bufA, *bufB;
    u64 *off, *wpk, *wdef;
    cudaGetSymbolAddress((void**)&bufA, g_bufA);
    cudaGetSymbolAddress((void**)&bufB, g_bufB);
    cudaGetSymbolAddress((void**)&off,  g_off);
    cudaGetSymbolAddress((void**)&wpk,  g_wpk);
    cudaGetSymbolAddress((void**)&wdef, g_wdef);

    PackArgs pa = { OW(1), OW(2), OW(3), OW(4), OW(5), OW(6),
                    WW(1), WW(2), WW(3), WW(4), WW(5), WW(6) };
    pack_all_k<<<(PACK_TOTAL + 255) / 256, 256>>>(pa, wpk, wdef);

    // stage 1: (1 -> 16), K=3, 33 -> 31, relu
    launch_off<1, 3, 33, 1, 3>(x, wpk + O1, OB(1), off);
    launch_def<1, 16, 3, 33, 4, true, 1>(x, off, wdef + E1, BB(1), bufA);
    // stage 2: (16 -> 32), K=3, 31 -> 29, relu
    launch_off<16, 3, 31, 1, 3>(bufA, wpk + O2, OB(2), off);
    launch_def<16, 32, 3, 31, 2, true, 1>(bufA, off, wdef + E2, BB(2), bufB);
    // stage 3: (32 -> 16), K=5, 29 -> 25, no relu  (image in 2 channel halves)
    launch_off<32, 5, 29, 2, 3>(bufB, wpk + O3, OB(3), off);
    launch_def<32, 16, 5, 29, 3, false, 2>(bufB, off, wdef + E3, BB(3), bufA);
    // stage 4: (16 -> 16), K=7, 25 -> 19, relu
    launch_off<16, 7, 25, 2, 3>(bufA, wpk + O4, OB(4), off);
    launch_def<16, 16, 7, 25, 2, true, 1>(bufA, off, wdef + E4, BB(4), bufB);
    // stage 5: (16 -> 8), K=5, 19 -> 15, relu
    launch_off<16, 5, 19, 1, 3>(bufB, wpk + O5, OB(5), off);
    launch_def<16, 8, 5, 19, 1, true, 1>(bufB, off, wdef + E5, BB(5), bufA);
    // stage 6: (8 -> 4), K=3, 15 -> 13, relu
    launch_off<8, 3, 15, 1, 3>(bufA, wpk + O6, OB(6), off);
    launch_def<8, 4, 3, 15, 1, true, 1>(bufA, off, wdef + E6, BB(6), bufB);

    fc4_k<<<128, 256>>>(bufB, fc1w, fc1b, fc2w, fc2b, (float*)d_out);
}